// round 12
// baseline (speedup 1.0000x reference)
#include <cuda_runtime.h>

#define BATCH 4096
#define NU    20
#define DZ    6
#define NCOL  120

// Output regions (floats): f1 | g1 | f2 | g2
#define F1OFF 0
#define G1OFF (BATCH * NU)
#define F2OFF (G1OFF + BATCH * NU * NCOL)
#define G2OFF (F2OFF + BATCH * NCOL)

// ---- shared memory float offsets (16B-aligned buffers) ----
#define W1A  0        /* 48  */
#define B1A  48       /* 16  */
#define W1B  64       /* 512 */
#define B1B  576      /* 32  */
#define W2A  608      /* 48  */
#define B2A  656      /* 16  */
#define W2B  672      /* 512 */
#define B2B  1184     /* 32  */
#define B1C  1216     /* 16  */
#define B2C  1232     /* 16  */
#define WCD  1248     /* dup'd C-weights [m][n16][k32*2], row stride 68 -> 2176 */
#define SXH  3424     /* 24: [0]=x[19], [1..20]=x[0..19], [21]=x[0] */
#define HA1  3448     /* 20*16 */
#define HA2  3784     /* +336 => bank-disjoint halves */
#define HB_I 4104     /* pair [m][sp10][k32][2] : 1280 */
#define HC_I 5384     /* pair [m][sp10][k16][2] : 640  */
#define SMEM_FLOATS 6024

#define PACK2(d, lo, hi) \
    asm("mov.b64 %0, {%1, %2};" : "=l"(d) : "f"(lo), "f"(hi))
#define UNPACK2(lo, hi, s) \
    asm("mov.b64 {%0, %1}, %2;" : "=f"(lo), "=f"(hi) : "l"(s))
#define FMA2(d, a, b, c) \
    asm("fma.rn.f32x2 %0, %1, %2, %3;" : "=l"(d) : "l"(a), "l"(b), "l"(c))
#define ADD2(d, a, b) \
    asm("add.rn.f32x2 %0, %1, %2;" : "=l"(d) : "l"(a), "l"(b))

// two-chain scalar dot product (phase B)
#define DOT16_2(acc, h4p, w0, w1, w2, w3)                                   \
    {                                                                       \
        float4 h0 = (h4p)[0], h1 = (h4p)[1], h2 = (h4p)[2], h3 = (h4p)[3];  \
        float a0 = h0.x*w0.x + h0.y*w0.y + h0.z*w0.z + h0.w*w0.w            \
                 + h1.x*w1.x + h1.y*w1.y + h1.z*w1.z + h1.w*w1.w;           \
        float a1 = h2.x*w2.x + h2.y*w2.y + h2.z*w2.z + h2.w*w2.w            \
                 + h3.x*w3.x + h3.y*w3.y + h3.z*w3.z + h3.w*w3.w;           \
        acc += a0 + a1;                                                     \
    }

__global__ __launch_bounds__(256, 4) void CGN_fused_kernel(
    const float* __restrict__ x,
    const float* __restrict__ w1a, const float* __restrict__ bb1a,
    const float* __restrict__ w1b, const float* __restrict__ bb1b,
    const float* __restrict__ w1c, const float* __restrict__ bb1c,
    const float* __restrict__ w1d, const float* __restrict__ bb1d,
    const float* __restrict__ w2a, const float* __restrict__ bb2a,
    const float* __restrict__ w2b, const float* __restrict__ bb2b,
    const float* __restrict__ w2c, const float* __restrict__ bb2c,
    const float* __restrict__ w2d, const float* __restrict__ bb2d,
    float* __restrict__ out)
{
    __shared__ __align__(16) float sm[SMEM_FLOATS];
    const int tid = threadIdx.x;
    const int b   = blockIdx.x;

    float* g1o = out + G1OFF + (size_t)b * (NU * NCOL);
    float* g2o = out + G2OFF + (size_t)b * (NCOL * NCOL);

    // ---- Phase Z: zero-fill g1 & g2 with pure wide stores ----
    {
        const float4 z4 = make_float4(0.f, 0.f, 0.f, 0.f);
        float4* p1 = reinterpret_cast<float4*>(g1o);
        for (int q = tid; q < 600; q += 256) p1[q] = z4;
        float4* p2 = reinterpret_cast<float4*>(g2o);
        for (int q = tid; q < 3600; q += 256) p2[q] = z4;
    }

    // ---- stage weights + x row (halo) into smem ----
    #define CP(off, src, n) for (int i = tid; i < (n); i += 256) sm[(off) + i] = (src)[i];
    CP(W1A, w1a, 48)   CP(B1A, bb1a, 16)
    CP(W1B, w1b, 512)  CP(B1B, bb1b, 32)
    CP(W2A, w2a, 48)   CP(B2A, bb2a, 16)
    CP(W2B, w2b, 512)  CP(B2B, bb2b, 32)
    CP(B1C, bb1c, 16)  CP(B2C, bb2c, 16)
    #undef CP
    // duplicated C-weights: sm[WCD + m*1088 + n*68 + k*2 + {0,1}] = wc[k*16+n]
    for (int i = tid; i < 2048; i += 256) {
        int m = i >> 10, r = i & 1023;
        int n = r >> 6;
        int k = (r >> 1) & 31;
        float v = (m ? w2c : w1c)[k * 16 + n];
        sm[WCD + m * 1088 + n * 68 + k * 2 + (i & 1)] = v;
    }
    if (tid < 20) {
        float v = x[(size_t)b * NU + tid];
        sm[SXH + 1 + tid] = v;
        if (tid == 19) sm[SXH]      = v;
        if (tid == 0)  sm[SXH + 21] = v;
    }
    __syncthreads();

    // ---- Phase A: layer a (3 -> 16), 640 tasks ----
    for (int task = tid; task < 640; task += 256) {
        int site = task >> 5;
        int n    = task & 31;
        float x0 = sm[SXH + site];
        float x1 = sm[SXH + site + 1];
        float x2 = sm[SXH + site + 2];
        bool m1 = n < 16;
        int  nn = n & 15;
        const float* W = m1 ? &sm[W1A] : &sm[W2A];
        float bias     = m1 ? sm[B1A + nn] : sm[B2A + nn];
        float acc = bias + x0 * W[nn] + x1 * W[16 + nn] + x2 * W[32 + nn];
        sm[(m1 ? HA1 : HA2) + site * 16 + nn] = fmaxf(acc, 0.f);
    }
    __syncthreads();

    // ---- Phase B: layer b (16 -> 32). 256 tasks; stores pair-interleaved ----
    {
        int n  = tid & 63;
        int sg = tid >> 6;
        bool m1 = n < 32;
        int  nn = n & 31;
        const float* W = m1 ? &sm[W1B] : &sm[W2B];
        float bias     = m1 ? sm[B1B + nn] : sm[B2B + nn];
        float w[16];
        #pragma unroll
        for (int k = 0; k < 16; k++) w[k] = W[k * 32 + nn];
        float4 w0 = make_float4(w[0],  w[1],  w[2],  w[3]);
        float4 w1 = make_float4(w[4],  w[5],  w[6],  w[7]);
        float4 w2 = make_float4(w[8],  w[9],  w[10], w[11]);
        float4 w3 = make_float4(w[12], w[13], w[14], w[15]);
        int ha  = m1 ? HA1 : HA2;
        int hbb = HB_I + (m1 ? 0 : 640);
        #pragma unroll
        for (int s5 = 0; s5 < 5; s5++) {
            int s = sg * 5 + s5;
            const float4* h4 = reinterpret_cast<const float4*>(&sm[ha + s * 16]);
            float acc = bias;
            DOT16_2(acc, h4, w0, w1, w2, w3);
            sm[hbb + (s >> 1) * 64 + nn * 2 + (s & 1)] = fmaxf(acc, 0.f);
        }
    }
    __syncthreads();

    // ---- Phase C: layer c (32 -> 16), paired f32x2, two chains.
    //      320 tasks (nn16, m, sp10). w: dup'd LDS.128; h: broadcast LDS.128 ----
    for (int t = tid; t < 320; t += 256) {
        int nn = t & 15;
        int m  = (t >> 4) & 1;
        int sp = t >> 5;
        const ulonglong2* wd = reinterpret_cast<const ulonglong2*>(
            &sm[WCD + m * 1088 + nn * 68]);
        const ulonglong2* hd = reinterpret_cast<const ulonglong2*>(
            &sm[HB_I + m * 640 + sp * 64]);
        float bias = sm[(m ? B2C : B1C) + nn];
        unsigned long long acc0, acc1;
        PACK2(acc0, bias, bias);
        PACK2(acc1, 0.f, 0.f);
        #pragma unroll
        for (int j = 0; j < 8; j++) {
            ulonglong2 wv = wd[j],     hv = hd[j];
            ulonglong2 wu = wd[j + 8], hu = hd[j + 8];
            FMA2(acc0, wv.x, hv.x, acc0);
            FMA2(acc0, wv.y, hv.y, acc0);
            FMA2(acc1, wu.x, hu.x, acc1);
            FMA2(acc1, wu.y, hu.y, acc1);
        }
        ADD2(acc0, acc0, acc1);
        float lo, hi;
        UNPACK2(lo, hi, acc0);
        sm[HC_I + m * 320 + sp * 32 + nn * 2]     = fmaxf(lo, 0.f);
        sm[HC_I + m * 320 + sp * 32 + nn * 2 + 1] = fmaxf(hi, 0.f);
    }
    __syncthreads();

    // ---- Phase D: output layer + banded scatter, paired f32x2, two chains.
    //      410 groups = 205 neurons x 2 site-halves (5 pairs each). ----
    for (int g = tid; g < 410; g += 256) {
        int nrn = g, half = 0;
        if (g >= 205) { nrn = g - 205; half = 1; }
        bool is1 = nrn < 19;
        int m = nrn - 19;

        float wf[16], bias;
        if (is1) {
            #pragma unroll
            for (int k = 0; k < 16; k++) wf[k] = w1d[k * 19 + nrn];
            bias = bb1d[nrn];
        } else {
            #pragma unroll
            for (int k = 0; k < 16; k++) wf[k] = w2d[k * 186 + m];
            bias = bb2d[m];
        }
        unsigned long long w2r[16], bias2;
        #pragma unroll
        for (int k = 0; k < 16; k++) PACK2(w2r[k], wf[k], wf[k]);
        PACK2(bias2, bias, bias);

        int s0 = half * 10;
        int cls, zq = 0, col = 0;
        if (is1) {
            if (nrn == 0) cls = 0;
            else {
                cls = 1;
                col = ((s0 + 19) % 20) * 6 + (nrn - 1);
                if (col >= 120) col -= 120;
            }
        } else if (m < 6) {
            cls = 2;
        } else {
            cls = 3;
            zq = (m - 6) / 30;
            int jq = (m - 6) - zq * 30;
            col = ((s0 + 18) % 20) * 6 + jq;
            if (col >= 120) col -= 120;
        }

        int hcb = HC_I + (is1 ? 0 : 320);
        #pragma unroll
        for (int pp = 0; pp < 5; pp++) {
            int sp = half * 5 + pp;
            int s  = 2 * sp;
            const ulonglong2* hd = reinterpret_cast<const ulonglong2*>(&sm[hcb + sp * 32]);
            unsigned long long acc0 = bias2, acc1;
            PACK2(acc1, 0.f, 0.f);
            #pragma unroll
            for (int j = 0; j < 4; j++) {
                ulonglong2 hv = hd[j];
                ulonglong2 hu = hd[j + 4];
                FMA2(acc0, w2r[2 * j],     hv.x, acc0);
                FMA2(acc0, w2r[2 * j + 1], hv.y, acc0);
                FMA2(acc1, w2r[2 * j + 8], hu.x, acc1);
                FMA2(acc1, w2r[2 * j + 9], hu.y, acc1);
            }
            ADD2(acc0, acc0, acc1);
            float aA, aB;
            UNPACK2(aA, aB, acc0);
            if (cls == 0) {
                out[F1OFF + (size_t)b * NU + s]     = aA;
                out[F1OFF + (size_t)b * NU + s + 1] = aB;
            } else if (cls == 1) {
                g1o[s * 120 + col] = aA;       col += 6; if (col >= 120) col -= 120;
                g1o[(s + 1) * 120 + col] = aB; col += 6; if (col >= 120) col -= 120;
            } else if (cls == 2) {
                out[F2OFF + (size_t)b * NCOL + s * 6 + m]       = aA;
                out[F2OFF + (size_t)b * NCOL + (s + 1) * 6 + m] = aB;
            } else {
                g2o[(s * 6 + zq) * 120 + col] = aA;       col += 6; if (col >= 120) col -= 120;
                g2o[((s + 1) * 6 + zq) * 120 + col] = aB; col += 6; if (col >= 120) col -= 120;
            }
        }
    }
}

extern "C" void kernel_launch(void* const* d_in, const int* in_sizes, int n_in,
                              void* d_out, int out_size) {
    const float* x   = (const float*)d_in[0];
    const float* w1a = (const float*)d_in[1];
    const float* b1a = (const float*)d_in[2];
    const float* w1b = (const float*)d_in[3];
    const float* b1b = (const float*)d_in[4];
    const float* w1c = (const float*)d_in[5];
    const float* b1c = (const float*)d_in[6];
    const float* w1d = (const float*)d_in[7];
    const float* b1d = (const float*)d_in[8];
    const float* w2a = (const float*)d_in[9];
    const float* b2a = (const float*)d_in[10];
    const float* w2b = (const float*)d_in[11];
    const float* b2b = (const float*)d_in[12];
    const float* w2c = (const float*)d_in[13];
    const float* b2c = (const float*)d_in[14];
    const float* w2d = (const float*)d_in[15];
    const float* b2d = (const float*)d_in[16];

    CGN_fused_kernel<<<BATCH, 256>>>(
        x, w1a, b1a, w1b, b1b, w1c, b1c, w1d, b1d,
        w2a, b2a, w2b, b2b, w2c, b2c, w2d, b2d,
        (float*)d_out);
}

// round 14
// speedup vs baseline: 1.0878x; 1.0878x over previous
#include <cuda_runtime.h>

#define BATCH 4096
#define NU    20
#define DZ    6
#define NCOL  120

// Output regions (floats): f1 | g1 | f2 | g2
#define F1OFF 0
#define G1OFF (BATCH * NU)
#define F2OFF (G1OFF + BATCH * NU * NCOL)
#define G2OFF (F2OFF + BATCH * NCOL)

// Shared-memory float offsets (all buffers 16B-aligned)
#define W1A 0
#define B1A 48
#define W1B 64
#define B1B 576
#define W1C 608
#define B1C 1120
#define W2A 1136
#define B2A 1184
#define W2B 1200
#define B2B 1712
#define W2C 1744
#define B2C 2256
#define SXH 2272        /* 24: [0]=x[19], [1..20]=x[0..19], [21]=x[0] */
#define HA1 2296        /* 20*16 */
#define HA2 2632        /* +336 pad => bank-disjoint halves */
#define HC1 HA1
#define HC2 HA2
#define HB1 2952        /* 20*32 */
#define HB2 3592
#define SMEM_FLOATS 4232

// two-chain dot product on 16 scalar weights (no float4 reg duplicates)
#define DOT16_2S(acc, h4p, w)                                               \
    {                                                                       \
        float4 h0 = (h4p)[0], h1 = (h4p)[1], h2 = (h4p)[2], h3 = (h4p)[3];  \
        float a0 = h0.x*(w)[0]  + h0.y*(w)[1]  + h0.z*(w)[2]  + h0.w*(w)[3] \
                 + h1.x*(w)[4]  + h1.y*(w)[5]  + h1.z*(w)[6]  + h1.w*(w)[7];\
        float a1 = h2.x*(w)[8]  + h2.y*(w)[9]  + h2.z*(w)[10] + h2.w*(w)[11]\
                 + h3.x*(w)[12] + h3.y*(w)[13] + h3.z*(w)[14] + h3.w*(w)[15];\
        acc += a0 + a1;                                                     \
    }

__global__ __launch_bounds__(256, 5) void CGN_fused_kernel(
    const float* __restrict__ x,
    const float* __restrict__ w1a, const float* __restrict__ bb1a,
    const float* __restrict__ w1b, const float* __restrict__ bb1b,
    const float* __restrict__ w1c, const float* __restrict__ bb1c,
    const float* __restrict__ w1d, const float* __restrict__ bb1d,
    const float* __restrict__ w2a, const float* __restrict__ bb2a,
    const float* __restrict__ w2b, const float* __restrict__ bb2b,
    const float* __restrict__ w2c, const float* __restrict__ bb2c,
    const float* __restrict__ w2d, const float* __restrict__ bb2d,
    float* __restrict__ out)
{
    __shared__ __align__(16) float sm[SMEM_FLOATS];
    const int tid = threadIdx.x;
    const int b   = blockIdx.x;

    float* g1o = out + G1OFF + (size_t)b * (NU * NCOL);
    float* g2o = out + G2OFF + (size_t)b * (NCOL * NCOL);

    // ---- Phase Z: zero-fill g1 & g2 with pure wide stores ----
    {
        const float4 z4 = make_float4(0.f, 0.f, 0.f, 0.f);
        float4* p1 = reinterpret_cast<float4*>(g1o);
        for (int q = tid; q < 600; q += 256) p1[q] = z4;
        float4* p2 = reinterpret_cast<float4*>(g2o);
        for (int q = tid; q < 3600; q += 256) p2[q] = z4;
    }

    // ---- stage abc-layer weights + x row (halo) into smem ----
    #define CP(off, src, n) for (int i = tid; i < (n); i += 256) sm[(off) + i] = (src)[i];
    CP(W1A, w1a, 48)   CP(B1A, bb1a, 16)
    CP(W1B, w1b, 512)  CP(B1B, bb1b, 32)
    CP(W1C, w1c, 512)  CP(B1C, bb1c, 16)
    CP(W2A, w2a, 48)   CP(B2A, bb2a, 16)
    CP(W2B, w2b, 512)  CP(B2B, bb2b, 32)
    CP(W2C, w2c, 512)  CP(B2C, bb2c, 16)
    #undef CP
    if (tid < 20) {
        float v = x[(size_t)b * NU + tid];
        sm[SXH + 1 + tid] = v;
        if (tid == 19) sm[SXH]      = v;
        if (tid == 0)  sm[SXH + 21] = v;
    }
    __syncthreads();

    // ---- Phase A: layer a (3 -> 16), both MLPs, 20 sites. 640 tasks ----
    for (int task = tid; task < 640; task += 256) {
        int site = task >> 5;
        int n    = task & 31;
        float x0 = sm[SXH + site];
        float x1 = sm[SXH + site + 1];
        float x2 = sm[SXH + site + 2];
        bool m1 = n < 16;
        int  nn = n & 15;
        const float* W = m1 ? &sm[W1A] : &sm[W2A];
        float bias     = m1 ? sm[B1A + nn] : sm[B2A + nn];
        float acc = bias + x0 * W[nn] + x1 * W[16 + nn] + x2 * W[32 + nn];
        sm[(m1 ? HA1 : HA2) + site * 16 + nn] = fmaxf(acc, 0.f);
    }
    __syncthreads();

    // ---- Phase B: layer b (16 -> 32). 256 tasks: 64 neurons x 4 site-groups ----
    {
        int n  = tid & 63;
        int sg = tid >> 6;
        bool m1 = n < 32;
        int  nn = n & 31;
        const float* W = m1 ? &sm[W1B] : &sm[W2B];
        float bias     = m1 ? sm[B1B + nn] : sm[B2B + nn];
        float w[16];
        #pragma unroll
        for (int k = 0; k < 16; k++) w[k] = W[k * 32 + nn];
        int ha = m1 ? HA1 : HA2;
        int hb = m1 ? HB1 : HB2;
        #pragma unroll
        for (int s5 = 0; s5 < 5; s5++) {
            int s = sg * 5 + s5;
            const float4* h4 = reinterpret_cast<const float4*>(&sm[ha + s * 16]);
            float acc = bias;
            DOT16_2S(acc, h4, w);
            sm[hb + s * 32 + nn] = fmaxf(acc, 0.f);
        }
    }
    __syncthreads();

    // ---- Phase C: layer c (32 -> 16). 640 tasks, float4 h reads, 2 chains ----
    for (int task = tid; task < 640; task += 256) {
        int site = task >> 5;
        int n    = task & 31;
        bool m1 = n < 16;
        int  nn = m1 ? n : n - 16;
        const float* W = m1 ? &sm[W1C] : &sm[W2C];
        float bias     = m1 ? sm[B1C + nn] : sm[B2C + nn];
        const float4* h4 = reinterpret_cast<const float4*>(&sm[(m1 ? HB1 : HB2) + site * 32]);
        float a0 = bias, a1 = 0.f;
        #pragma unroll
        for (int k8 = 0; k8 < 4; k8++) {
            float4 ha_ = h4[k8];
            float4 hb_ = h4[k8 + 4];
            a0 += ha_.x * W[(4 * k8 + 0) * 16 + nn];
            a0 += ha_.y * W[(4 * k8 + 1) * 16 + nn];
            a0 += ha_.z * W[(4 * k8 + 2) * 16 + nn];
            a0 += ha_.w * W[(4 * k8 + 3) * 16 + nn];
            a1 += hb_.x * W[(4 * k8 + 16) * 16 + nn];
            a1 += hb_.y * W[(4 * k8 + 17) * 16 + nn];
            a1 += hb_.z * W[(4 * k8 + 18) * 16 + nn];
            a1 += hb_.w * W[(4 * k8 + 19) * 16 + nn];
        }
        sm[(m1 ? HC1 : HC2) + site * 16 + nn] = fmaxf(a0 + a1, 0.f);
    }
    __syncthreads();

    // ---- Phase D: output layer fused with banded scatter.
    //      820 groups = 205 neurons x 4 site-groups (5 sites each). ----
    for (int g = tid; g < 820; g += 256) {
        int nrn = g % 205;
        int sg  = g / 205;
        int s0  = sg * 5;
        bool is1 = nrn < 19;
        float w[16], bias;
        int m = 0;
        if (is1) {
            #pragma unroll
            for (int k = 0; k < 16; k++) w[k] = w1d[k * 19 + nrn];
            bias = bb1d[nrn];
        } else {
            m = nrn - 19;
            #pragma unroll
            for (int k = 0; k < 16; k++) w[k] = w2d[k * 186 + m];
            bias = bb2d[m];
        }

        int cls, zq = 0, col = 0;
        if (is1) {
            if (nrn == 0) cls = 0;
            else {
                cls = 1;
                col = ((s0 + 19) % 20) * 6 + (nrn - 1);
                if (col >= 120) col -= 120;
            }
        } else if (m < 6) {
            cls = 2;
        } else {
            cls = 3;
            zq = (m - 6) / 30;
            int jq = (m - 6) - zq * 30;
            col = ((s0 + 18) % 20) * 6 + jq;
            if (col >= 120) col -= 120;
        }

        int hc = is1 ? HC1 : HC2;
        #pragma unroll
        for (int s5 = 0; s5 < 5; s5++) {
            int s = s0 + s5;
            const float4* h4 = reinterpret_cast<const float4*>(&sm[hc + s * 16]);
            float acc = bias;
            DOT16_2S(acc, h4, w);
            if (cls == 0) {
                out[F1OFF + (size_t)b * NU + s] = acc;
            } else if (cls == 1) {
                g1o[s * 120 + col] = acc;
                col += 6; if (col >= 120) col -= 120;
            } else if (cls == 2) {
                out[F2OFF + (size_t)b * NCOL + s * 6 + m] = acc;
            } else {
                g2o[(s * 6 + zq) * 120 + col] = acc;
                col += 6; if (col >= 120) col -= 120;
            }
        }
    }
}

extern "C" void kernel_launch(void* const* d_in, const int* in_sizes, int n_in,
                              void* d_out, int out_size) {
    const float* x   = (const float*)d_in[0];
    const float* w1a = (const float*)d_in[1];
    const float* b1a = (const float*)d_in[2];
    const float* w1b = (const float*)d_in[3];
    const float* b1b = (const float*)d_in[4];
    const float* w1c = (const float*)d_in[5];
    const float* b1c = (const float*)d_in[6];
    const float* w1d = (const float*)d_in[7];
    const float* b1d = (const float*)d_in[8];
    const float* w2a = (const float*)d_in[9];
    const float* b2a = (const float*)d_in[10];
    const float* w2b = (const float*)d_in[11];
    const float* b2b = (const float*)d_in[12];
    const float* w2c = (const float*)d_in[13];
    const float* b2c = (const float*)d_in[14];
    const float* w2d = (const float*)d_in[15];
    const float* b2d = (const float*)d_in[16];

    CGN_fused_kernel<<<BATCH, 256>>>(
        x, w1a, b1a, w1b, b1b, w1c, b1c, w1d, b1d,
        w2a, b2a, w2b, b2b, w2c, b2c, w2d, b2d,
        (float*)d_out);
}

// round 16
// speedup vs baseline: 1.1554x; 1.0622x over previous
#include <cuda_runtime.h>

#define BATCH 4096
#define NU    20
#define DZ    6
#define NCOL  120

// Output regions (floats): f1 | g1 | f2 | g2
#define F1OFF 0
#define G1OFF (BATCH * NU)
#define F2OFF (G1OFF + BATCH * NU * NCOL)
#define G2OFF (F2OFF + BATCH * NCOL)

// Shared-memory float offsets (all buffers 16B-aligned)
#define W1A 0
#define B1A 48
#define W1B 64
#define B1B 576
#define W1C 608
#define B1C 1120
#define W2A 1136
#define B2A 1184
#define W2B 1200
#define B2B 1712
#define W2C 1744
#define B2C 2256
#define SXH 2272        /* 24: [0]=x[19], [1..20]=x[0..19], [21]=x[0] */
#define HA1 2296        /* 20*16 */
#define HA2 2632        /* +336 pad => bank-disjoint halves */
#define HC1 HA1
#define HC2 HA2
#define HB1 2952        /* 20*32 */
#define HB2 3592
#define SMEM_FLOATS 4232

// two-chain dot product on 16 scalar weights (no float4 reg duplicates)
#define DOT16_2S(acc, h4p, w)                                               \
    {                                                                       \
        float4 h0 = (h4p)[0], h1 = (h4p)[1], h2 = (h4p)[2], h3 = (h4p)[3];  \
        float a0 = h0.x*(w)[0]  + h0.y*(w)[1]  + h0.z*(w)[2]  + h0.w*(w)[3] \
                 + h1.x*(w)[4]  + h1.y*(w)[5]  + h1.z*(w)[6]  + h1.w*(w)[7];\
        float a1 = h2.x*(w)[8]  + h2.y*(w)[9]  + h2.z*(w)[10] + h2.w*(w)[11]\
                 + h3.x*(w)[12] + h3.y*(w)[13] + h3.z*(w)[14] + h3.w*(w)[15];\
        acc += a0 + a1;                                                     \
    }

__global__ __launch_bounds__(256, 5) void CGN_fused_kernel(
    const float* __restrict__ x,
    const float* __restrict__ w1a, const float* __restrict__ bb1a,
    const float* __restrict__ w1b, const float* __restrict__ bb1b,
    const float* __restrict__ w1c, const float* __restrict__ bb1c,
    const float* __restrict__ w1d, const float* __restrict__ bb1d,
    const float* __restrict__ w2a, const float* __restrict__ bb2a,
    const float* __restrict__ w2b, const float* __restrict__ bb2b,
    const float* __restrict__ w2c, const float* __restrict__ bb2c,
    const float* __restrict__ w2d, const float* __restrict__ bb2d,
    float* __restrict__ out)
{
    __shared__ __align__(16) float sm[SMEM_FLOATS];
    const int tid = threadIdx.x;
    const int b   = blockIdx.x;

    float* g1o = out + G1OFF + (size_t)b * (NU * NCOL);
    float* g2o = out + G2OFF + (size_t)b * (NCOL * NCOL);

    // ---- Phase Z: zero-fill g1 & g2 with pure wide stores ----
    {
        const float4 z4 = make_float4(0.f, 0.f, 0.f, 0.f);
        float4* p1 = reinterpret_cast<float4*>(g1o);
        for (int q = tid; q < 600; q += 256) p1[q] = z4;
        float4* p2 = reinterpret_cast<float4*>(g2o);
        for (int q = tid; q < 3600; q += 256) p2[q] = z4;
    }

    // ---- stage abc-layer weights + x row (halo) into smem ----
    #define CP(off, src, n) for (int i = tid; i < (n); i += 256) sm[(off) + i] = (src)[i];
    CP(W1A, w1a, 48)   CP(B1A, bb1a, 16)
    CP(W1B, w1b, 512)  CP(B1B, bb1b, 32)
    CP(W1C, w1c, 512)  CP(B1C, bb1c, 16)
    CP(W2A, w2a, 48)   CP(B2A, bb2a, 16)
    CP(W2B, w2b, 512)  CP(B2B, bb2b, 32)
    CP(W2C, w2c, 512)  CP(B2C, bb2c, 16)
    #undef CP
    if (tid < 20) {
        float v = x[(size_t)b * NU + tid];
        sm[SXH + 1 + tid] = v;
        if (tid == 19) sm[SXH]      = v;
        if (tid == 0)  sm[SXH + 21] = v;
    }
    __syncthreads();

    // ---- Phase A: layer a (3 -> 16), both MLPs, 20 sites. 640 tasks ----
    for (int task = tid; task < 640; task += 256) {
        int site = task >> 5;
        int n    = task & 31;
        float x0 = sm[SXH + site];
        float x1 = sm[SXH + site + 1];
        float x2 = sm[SXH + site + 2];
        bool m1 = n < 16;
        int  nn = n & 15;
        const float* W = m1 ? &sm[W1A] : &sm[W2A];
        float bias     = m1 ? sm[B1A + nn] : sm[B2A + nn];
        float acc = bias + x0 * W[nn] + x1 * W[16 + nn] + x2 * W[32 + nn];
        sm[(m1 ? HA1 : HA2) + site * 16 + nn] = fmaxf(acc, 0.f);
    }
    __syncthreads();

    // ---- Phase B: layer b (16 -> 32). 256 tasks: 64 neurons x 4 site-groups ----
    {
        int n  = tid & 63;
        int sg = tid >> 6;
        bool m1 = n < 32;
        int  nn = n & 31;
        const float* W = m1 ? &sm[W1B] : &sm[W2B];
        float bias     = m1 ? sm[B1B + nn] : sm[B2B + nn];
        float w[16];
        #pragma unroll
        for (int k = 0; k < 16; k++) w[k] = W[k * 32 + nn];
        int ha = m1 ? HA1 : HA2;
        int hb = m1 ? HB1 : HB2;
        #pragma unroll
        for (int s5 = 0; s5 < 5; s5++) {
            int s = sg * 5 + s5;
            const float4* h4 = reinterpret_cast<const float4*>(&sm[ha + s * 16]);
            float acc = bias;
            DOT16_2S(acc, h4, w);
            sm[hb + s * 32 + nn] = fmaxf(acc, 0.f);
        }
    }
    __syncthreads();

    // ---- Phase C: layer c (32 -> 16). Re-keyed: thread owns one (mlp, nn)
    //      column for all its sites {s0, s0+8, s0+16}; weight column loaded
    //      ONCE (two 16-reg halves). h reads are warp-broadcast LDS.128 ----
    {
        int n  = tid & 31;
        int s0 = tid >> 5;              // 0..7; sites {s0, s0+8, [s0+16 if s0<4]}
        bool m1 = n < 16;
        int  nn = n & 15;
        const float* W = m1 ? &sm[W1C] : &sm[W2C];
        float bias     = m1 ? sm[B1C + nn] : sm[B2C + nn];
        int hb = m1 ? HB1 : HB2;
        int hc = m1 ? HC1 : HC2;
        float acc0 = bias, acc1 = bias, acc2 = bias;
        // half 0: k = 0..15
        {
            float w[16];
            #pragma unroll
            for (int k = 0; k < 16; k++) w[k] = W[k * 16 + nn];
            const float4* h4a = reinterpret_cast<const float4*>(&sm[hb + s0 * 32]);
            DOT16_2S(acc0, h4a, w);
            const float4* h4b = reinterpret_cast<const float4*>(&sm[hb + (s0 + 8) * 32]);
            DOT16_2S(acc1, h4b, w);
            if (s0 < 4) {
                const float4* h4c = reinterpret_cast<const float4*>(&sm[hb + (s0 + 16) * 32]);
                DOT16_2S(acc2, h4c, w);
            }
        }
        // half 1: k = 16..31
        {
            float w[16];
            #pragma unroll
            for (int k = 0; k < 16; k++) w[k] = W[(16 + k) * 16 + nn];
            const float4* h4a = reinterpret_cast<const float4*>(&sm[hb + s0 * 32 + 16]);
            DOT16_2S(acc0, h4a, w);
            const float4* h4b = reinterpret_cast<const float4*>(&sm[hb + (s0 + 8) * 32 + 16]);
            DOT16_2S(acc1, h4b, w);
            if (s0 < 4) {
                const float4* h4c = reinterpret_cast<const float4*>(&sm[hb + (s0 + 16) * 32 + 16]);
                DOT16_2S(acc2, h4c, w);
            }
        }
        sm[hc + s0 * 16 + nn]       = fmaxf(acc0, 0.f);
        sm[hc + (s0 + 8) * 16 + nn] = fmaxf(acc1, 0.f);
        if (s0 < 4)
            sm[hc + (s0 + 16) * 16 + nn] = fmaxf(acc2, 0.f);
    }
    __syncthreads();

    // ---- Phase D: output layer fused with banded scatter.
    //      820 groups = 205 neurons x 4 site-groups (5 sites each). ----
    for (int g = tid; g < 820; g += 256) {
        int nrn = g % 205;
        int sg  = g / 205;
        int s0  = sg * 5;
        bool is1 = nrn < 19;
        float w[16], bias;
        int m = 0;
        if (is1) {
            #pragma unroll
            for (int k = 0; k < 16; k++) w[k] = w1d[k * 19 + nrn];
            bias = bb1d[nrn];
        } else {
            m = nrn - 19;
            #pragma unroll
            for (int k = 0; k < 16; k++) w[k] = w2d[k * 186 + m];
            bias = bb2d[m];
        }

        int cls, zq = 0, col = 0;
        if (is1) {
            if (nrn == 0) cls = 0;
            else {
                cls = 1;
                col = ((s0 + 19) % 20) * 6 + (nrn - 1);
                if (col >= 120) col -= 120;
            }
        } else if (m < 6) {
            cls = 2;
        } else {
            cls = 3;
            zq = (m - 6) / 30;
            int jq = (m - 6) - zq * 30;
            col = ((s0 + 18) % 20) * 6 + jq;
            if (col >= 120) col -= 120;
        }

        int hc = is1 ? HC1 : HC2;
        #pragma unroll
        for (int s5 = 0; s5 < 5; s5++) {
            int s = s0 + s5;
            const float4* h4 = reinterpret_cast<const float4*>(&sm[hc + s * 16]);
            float acc = bias;
            DOT16_2S(acc, h4, w);
            if (cls == 0) {
                out[F1OFF + (size_t)b * NU + s] = acc;
            } else if (cls == 1) {
                g1o[s * 120 + col] = acc;
                col += 6; if (col >= 120) col -= 120;
            } else if (cls == 2) {
                out[F2OFF + (size_t)b * NCOL + s * 6 + m] = acc;
            } else {
                g2o[(s * 6 + zq) * 120 + col] = acc;
                col += 6; if (col >= 120) col -= 120;
            }
        }
    }
}

extern "C" void kernel_launch(void* const* d_in, const int* in_sizes, int n_in,
                              void* d_out, int out_size) {
    const float* x   = (const float*)d_in[0];
    const float* w1a = (const float*)d_in[1];
    const float* b1a = (const float*)d_in[2];
    const float* w1b = (const float*)d_in[3];
    const float* b1b = (const float*)d_in[4];
    const float* w1c = (const float*)d_in[5];
    const float* b1c = (const float*)d_in[6];
    const float* w1d = (const float*)d_in[7];
    const float* b1d = (const float*)d_in[8];
    const float* w2a = (const float*)d_in[9];
    const float* b2a = (const float*)d_in[10];
    const float* w2b = (const float*)d_in[11];
    const float* b2b = (const float*)d_in[12];
    const float* w2c = (const float*)d_in[13];
    const float* b2c = (const float*)d_in[14];
    const float* w2d = (const float*)d_in[15];
    const float* b2d = (const float*)d_in[16];

    CGN_fused_kernel<<<BATCH, 256>>>(
        x, w1a, b1a, w1b, b1b, w1c, b1c, w1d, b1d,
        w2a, b2a, w2b, b2b, w2c, b2c, w2d, b2d,
        (float*)d_out);
}

// round 17
// speedup vs baseline: 1.1800x; 1.0213x over previous
#include <cuda_runtime.h>

#define BATCH 4096
#define NU    20
#define DZ    6
#define NCOL  120

// Output regions (floats): f1 | g1 | f2 | g2
#define F1OFF 0
#define G1OFF (BATCH * NU)
#define F2OFF (G1OFF + BATCH * NU * NCOL)
#define G2OFF (F2OFF + BATCH * NCOL)

// Shared-memory float offsets (all buffers 16B-aligned)
#define W1A 0
#define B1A 48
#define W1B 64
#define B1B 576
#define W1C 608
#define B1C 1120
#define W2A 1136
#define B2A 1184
#define W2B 1200
#define B2B 1712
#define W2C 1744
#define B2C 2256
#define SXH 2272        /* 24: [0]=x[19], [1..20]=x[0..19], [21]=x[0] */
#define HA1 2296        /* 20*16 */
#define HA2 2632        /* +336 pad => bank-disjoint halves */
#define HC1 HA1
#define HC2 HA2
#define HB1 2952        /* 20*32 */
#define HB2 3592
#define SMEM_FLOATS 4232

// two-chain dot product on 16 scalar weights (no float4 reg duplicates)
#define DOT16_2S(acc, h4p, w)                                               \
    {                                                                       \
        float4 h0 = (h4p)[0], h1 = (h4p)[1], h2 = (h4p)[2], h3 = (h4p)[3];  \
        float a0 = h0.x*(w)[0]  + h0.y*(w)[1]  + h0.z*(w)[2]  + h0.w*(w)[3] \
                 + h1.x*(w)[4]  + h1.y*(w)[5]  + h1.z*(w)[6]  + h1.w*(w)[7];\
        float a1 = h2.x*(w)[8]  + h2.y*(w)[9]  + h2.z*(w)[10] + h2.w*(w)[11]\
                 + h3.x*(w)[12] + h3.y*(w)[13] + h3.z*(w)[14] + h3.w*(w)[15];\
        acc += a0 + a1;                                                     \
    }

__global__ __launch_bounds__(256, 5) void CGN_fused_kernel(
    const float* __restrict__ x,
    const float* __restrict__ w1a, const float* __restrict__ bb1a,
    const float* __restrict__ w1b, const float* __restrict__ bb1b,
    const float* __restrict__ w1c, const float* __restrict__ bb1c,
    const float* __restrict__ w1d, const float* __restrict__ bb1d,
    const float* __restrict__ w2a, const float* __restrict__ bb2a,
    const float* __restrict__ w2b, const float* __restrict__ bb2b,
    const float* __restrict__ w2c, const float* __restrict__ bb2c,
    const float* __restrict__ w2d, const float* __restrict__ bb2d,
    float* __restrict__ out)
{
    __shared__ __align__(16) float sm[SMEM_FLOATS];
    const int tid = threadIdx.x;
    const int b   = blockIdx.x;

    float* g1o = out + G1OFF + (size_t)b * (NU * NCOL);
    float* g2o = out + G2OFF + (size_t)b * (NCOL * NCOL);

    // ---- Phase Z: zero-fill g1 & g2 with pure wide stores ----
    {
        const float4 z4 = make_float4(0.f, 0.f, 0.f, 0.f);
        float4* p1 = reinterpret_cast<float4*>(g1o);
        for (int q = tid; q < 600; q += 256) p1[q] = z4;
        float4* p2 = reinterpret_cast<float4*>(g2o);
        for (int q = tid; q < 3600; q += 256) p2[q] = z4;
    }

    // ---- stage abc-layer weights (float4 copies) + x row (halo) ----
    #define CP4(off, src, n)                                                     \
        for (int i = tid; i < (n) / 4; i += 256)                                 \
            reinterpret_cast<float4*>(&sm[(off)])[i] =                           \
                reinterpret_cast<const float4*>(src)[i];
    CP4(W1A, w1a, 48)   CP4(B1A, bb1a, 16)
    CP4(W1B, w1b, 512)  CP4(B1B, bb1b, 32)
    CP4(W1C, w1c, 512)  CP4(B1C, bb1c, 16)
    CP4(W2A, w2a, 48)   CP4(B2A, bb2a, 16)
    CP4(W2B, w2b, 512)  CP4(B2B, bb2b, 32)
    CP4(W2C, w2c, 512)  CP4(B2C, bb2c, 16)
    #undef CP4
    if (tid < 20) {
        float v = x[(size_t)b * NU + tid];
        sm[SXH + 1 + tid] = v;
        if (tid == 19) sm[SXH]      = v;
        if (tid == 0)  sm[SXH + 21] = v;
    }
    __syncthreads();

    // ---- Phase A: layer a (3 -> 16), both MLPs, 20 sites. 640 tasks ----
    for (int task = tid; task < 640; task += 256) {
        int site = task >> 5;
        int n    = task & 31;
        float x0 = sm[SXH + site];
        float x1 = sm[SXH + site + 1];
        float x2 = sm[SXH + site + 2];
        bool m1 = n < 16;
        int  nn = n & 15;
        const float* W = m1 ? &sm[W1A] : &sm[W2A];
        float bias     = m1 ? sm[B1A + nn] : sm[B2A + nn];
        float acc = bias + x0 * W[nn] + x1 * W[16 + nn] + x2 * W[32 + nn];
        sm[(m1 ? HA1 : HA2) + site * 16 + nn] = fmaxf(acc, 0.f);
    }
    __syncthreads();

    // ---- Phase B: layer b (16 -> 32). 256 tasks: 64 neurons x 4 site-groups ----
    {
        int n  = tid & 63;
        int sg = tid >> 6;
        bool m1 = n < 32;
        int  nn = n & 31;
        const float* W = m1 ? &sm[W1B] : &sm[W2B];
        float bias     = m1 ? sm[B1B + nn] : sm[B2B + nn];
        float w[16];
        #pragma unroll
        for (int k = 0; k < 16; k++) w[k] = W[k * 32 + nn];
        int ha = m1 ? HA1 : HA2;
        int hb = m1 ? HB1 : HB2;
        #pragma unroll
        for (int s5 = 0; s5 < 5; s5++) {
            int s = sg * 5 + s5;
            const float4* h4 = reinterpret_cast<const float4*>(&sm[ha + s * 16]);
            float acc = bias;
            DOT16_2S(acc, h4, w);
            sm[hb + s * 32 + nn] = fmaxf(acc, 0.f);
        }
    }
    __syncthreads();

    // ---- Phase C: layer c (32 -> 16). Thread owns one (mlp, nn) column for
    //      sites {s0, s0+8, [s0+16]}; weight column loaded once (two halves) ----
    {
        int n  = tid & 31;
        int s0 = tid >> 5;              // 0..7
        bool m1 = n < 16;
        int  nn = n & 15;
        const float* W = m1 ? &sm[W1C] : &sm[W2C];
        float bias     = m1 ? sm[B1C + nn] : sm[B2C + nn];
        int hb = m1 ? HB1 : HB2;
        int hc = m1 ? HC1 : HC2;
        float acc0 = bias, acc1 = bias, acc2 = bias;
        // half 0: k = 0..15
        {
            float w[16];
            #pragma unroll
            for (int k = 0; k < 16; k++) w[k] = W[k * 16 + nn];
            const float4* h4a = reinterpret_cast<const float4*>(&sm[hb + s0 * 32]);
            DOT16_2S(acc0, h4a, w);
            const float4* h4b = reinterpret_cast<const float4*>(&sm[hb + (s0 + 8) * 32]);
            DOT16_2S(acc1, h4b, w);
            if (s0 < 4) {
                const float4* h4c = reinterpret_cast<const float4*>(&sm[hb + (s0 + 16) * 32]);
                DOT16_2S(acc2, h4c, w);
            }
        }
        // half 1: k = 16..31
        {
            float w[16];
            #pragma unroll
            for (int k = 0; k < 16; k++) w[k] = W[(16 + k) * 16 + nn];
            const float4* h4a = reinterpret_cast<const float4*>(&sm[hb + s0 * 32 + 16]);
            DOT16_2S(acc0, h4a, w);
            const float4* h4b = reinterpret_cast<const float4*>(&sm[hb + (s0 + 8) * 32 + 16]);
            DOT16_2S(acc1, h4b, w);
            if (s0 < 4) {
                const float4* h4c = reinterpret_cast<const float4*>(&sm[hb + (s0 + 16) * 32 + 16]);
                DOT16_2S(acc2, h4c, w);
            }
        }
        sm[hc + s0 * 16 + nn]       = fmaxf(acc0, 0.f);
        sm[hc + (s0 + 8) * 16 + nn] = fmaxf(acc1, 0.f);
        if (s0 < 4)
            sm[hc + (s0 + 16) * 16 + nn] = fmaxf(acc2, 0.f);
    }
    __syncthreads();

    // ---- Phase D: output layer + banded scatter.
    //      ONE NEURON PER THREAD (tid<205), all 20 sites: weight column and
    //      scatter class computed once; incremental band columns. ----
    if (tid < 205) {
        const int nrn = tid;
        bool is1 = nrn < 19;
        int m = nrn - 19;
        float w[16], bias;
        if (is1) {
            #pragma unroll
            for (int k = 0; k < 16; k++) w[k] = w1d[k * 19 + nrn];
            bias = bb1d[nrn];
        } else {
            #pragma unroll
            for (int k = 0; k < 16; k++) w[k] = w2d[k * 186 + m];
            bias = bb2d[m];
        }

        int cls, zq = 0, col = 0;
        if (is1) {
            if (nrn == 0) cls = 0;
            else {
                cls = 1;
                col = 114 + (nrn - 1);          // ((0+19)%20)*6 + j
                if (col >= 120) col -= 120;
            }
        } else if (m < 6) {
            cls = 2;
        } else {
            cls = 3;
            zq = (m - 6) / 30;
            int jq = (m - 6) - zq * 30;
            col = 108 + jq;                      // ((0+18)%20)*6 + j
            if (col >= 120) col -= 120;
        }

        int hc = is1 ? HC1 : HC2;
        #pragma unroll 4
        for (int s = 0; s < 20; s++) {
            const float4* h4 = reinterpret_cast<const float4*>(&sm[hc + s * 16]);
            float acc = bias;
            DOT16_2S(acc, h4, w);
            if (cls == 0) {
                out[F1OFF + (size_t)b * NU + s] = acc;
            } else if (cls == 1) {
                g1o[s * 120 + col] = acc;
                col += 6; if (col >= 120) col -= 120;
            } else if (cls == 2) {
                out[F2OFF + (size_t)b * NCOL + s * 6 + m] = acc;
            } else {
                g2o[(s * 6 + zq) * 120 + col] = acc;
                col += 6; if (col >= 120) col -= 120;
            }
        }
    }
}

extern "C" void kernel_launch(void* const* d_in, const int* in_sizes, int n_in,
                              void* d_out, int out_size) {
    const float* x   = (const float*)d_in[0];
    const float* w1a = (const float*)d_in[1];
    const float* b1a = (const float*)d_in[2];
    const float* w1b = (const float*)d_in[3];
    const float* b1b = (const float*)d_in[4];
    const float* w1c = (const float*)d_in[5];
    const float* b1c = (const float*)d_in[6];
    const float* w1d = (const float*)d_in[7];
    const float* b1d = (const float*)d_in[8];
    const float* w2a = (const float*)d_in[9];
    const float* b2a = (const float*)d_in[10];
    const float* w2b = (const float*)d_in[11];
    const float* b2b = (const float*)d_in[12];
    const float* w2c = (const float*)d_in[13];
    const float* b2c = (const float*)d_in[14];
    const float* w2d = (const float*)d_in[15];
    const float* b2d = (const float*)d_in[16];

    CGN_fused_kernel<<<BATCH, 256>>>(
        x, w1a, b1a, w1b, b1b, w1c, b1c, w1d, b1d,
        w2a, b2a, w2b, b2b, w2c, b2c, w2d, b2d,
        (float*)d_out);
}